// round 12
// baseline (speedup 1.0000x reference)
#include <cuda_runtime.h>

// HierarchyInvertClassifier: out[b,k,h,w] = bias[k] + sum_{c in group k} w[c]*in[b,c,h,w]
// B=8, C=64, H=W=512, K=12. Groups are contiguous channel ranges (static).
//
// HBM-bound pure stream: 512 MiB read + 96 MiB write, zero reuse.
// R12: ILP=4 probe — four independent LDG streams per channel iteration
// (logical extreme of the per-warp-MLP lever; R10 showed ILP=2 gave the
// best DRAM%). 64-thr blocks, 2048 blocks, budget (64,8)=128 regs.
// Fallback: R11 (ILP=2, 64t, 4096blk) at 96.16us if this is neutral/worse.

#define HW    (512 * 512)
#define HW4   (HW / 4)        // 65536 float4 per plane
#define CCH   64
#define KOUT  12
#define TPB   64              // threads per block
#define ILP   4
#define VPB   (ILP * TPB)     // vec positions per block = 256
#define BLKPI (HW4 / VPB)     // blocks per image = 256

__constant__ int kGroupStart[KOUT + 1] = {0, 1, 4, 14, 20, 28, 38, 46, 52, 57, 59, 62, 64};

__global__ __launch_bounds__(TPB, 8)
void hier_invert_kernel(const float4* __restrict__ in4,
                        const float*  __restrict__ w,
                        const float*  __restrict__ bias,
                        float4* __restrict__ out4)
{
    __shared__ float sw[CCH];
    __shared__ float sb[KOUT];
    int t = threadIdx.x;
    sw[t] = w[t];
    if (t < KOUT) sb[t] = bias[t];
    __syncthreads();

    int bimg = blockIdx.x >> 8;               // image index (0..7), 256 blocks/image
    int blk  = blockIdx.x & (BLKPI - 1);      // block within image
    int p0   = blk * VPB + t;                 // first vec position; others at +TPB,+2TPB,+3TPB

    const float4* ip = in4 + ((long)bimg * CCH) * HW4 + p0;
    float4*       op = out4 + ((long)bimg * KOUT) * HW4 + p0;

    #pragma unroll
    for (int k = 0; k < KOUT; k++) {
        const int c0 = kGroupStart[k];
        const int c1 = kGroupStart[k + 1];
        float bk = sb[k];
        float4 a0 = make_float4(bk, bk, bk, bk);
        float4 a1 = a0, a2 = a0, a3 = a0;
        #pragma unroll
        for (int c = c0; c < c1; c++) {
            const float4* p = ip + (long)c * HW4;
            float4 v0 = __ldcs(p);
            float4 v1 = __ldcs(p + TPB);
            float4 v2 = __ldcs(p + 2 * TPB);
            float4 v3 = __ldcs(p + 3 * TPB);
            float  wc = sw[c];
            a0.x = fmaf(wc, v0.x, a0.x); a0.y = fmaf(wc, v0.y, a0.y);
            a0.z = fmaf(wc, v0.z, a0.z); a0.w = fmaf(wc, v0.w, a0.w);
            a1.x = fmaf(wc, v1.x, a1.x); a1.y = fmaf(wc, v1.y, a1.y);
            a1.z = fmaf(wc, v1.z, a1.z); a1.w = fmaf(wc, v1.w, a1.w);
            a2.x = fmaf(wc, v2.x, a2.x); a2.y = fmaf(wc, v2.y, a2.y);
            a2.z = fmaf(wc, v2.z, a2.z); a2.w = fmaf(wc, v2.w, a2.w);
            a3.x = fmaf(wc, v3.x, a3.x); a3.y = fmaf(wc, v3.y, a3.y);
            a3.z = fmaf(wc, v3.z, a3.z); a3.w = fmaf(wc, v3.w, a3.w);
        }
        float4* q = op + (long)k * HW4;
        __stcs(q, a0);
        __stcs(q + TPB, a1);
        __stcs(q + 2 * TPB, a2);
        __stcs(q + 3 * TPB, a3);
    }
}

extern "C" void kernel_launch(void* const* d_in, const int* in_sizes, int n_in,
                              void* d_out, int out_size)
{
    const float* pred_lr = (const float*)d_in[0];   // [8,64,512,512]
    const float* weights = (const float*)d_in[1];   // [64]
    const float* biases  = (const float*)d_in[2];   // [12]
    float* out = (float*)d_out;                     // [8,12,512,512]

    int blocks = 8 * BLKPI;                         // 2048

    hier_invert_kernel<<<blocks, TPB>>>(
        (const float4*)pred_lr, weights, biases, (float4*)out);
}

// round 13
// speedup vs baseline: 1.0213x; 1.0213x over previous
#include <cuda_runtime.h>

// HierarchyInvertClassifier: out[b,k,h,w] = bias[k] + sum_{c in group k} w[c]*in[b,c,h,w]
// B=8, C=64, H=W=512, K=12. Groups are contiguous channel ranges (static).
//
// HBM-bound pure stream: 512 MiB read + 96 MiB write, zero reuse.
// R13 = ILP=4 (best stream phase: ncu 92.3us, DRAM 83.5%, R12)
//     x 4096 blocks (best tail: R4/R11) via 32-thread blocks (VPB=128).
// ~19 blocks/SM reg-limited = 19 warps/SM, >= R12's achieved occupancy,
// with half the per-block drain quantum.

#define HW    (512 * 512)
#define HW4   (HW / 4)        // 65536 float4 per plane
#define CCH   64
#define KOUT  12
#define TPB   32              // threads per block (one warp)
#define ILP   4
#define VPB   (ILP * TPB)     // vec positions per block = 128
#define BLKPI (HW4 / VPB)     // blocks per image = 512

__constant__ int kGroupStart[KOUT + 1] = {0, 1, 4, 14, 20, 28, 38, 46, 52, 57, 59, 62, 64};

__global__ __launch_bounds__(TPB)
void hier_invert_kernel(const float4* __restrict__ in4,
                        const float*  __restrict__ w,
                        const float*  __restrict__ bias,
                        float4* __restrict__ out4)
{
    __shared__ float sw[CCH];
    __shared__ float sb[KOUT];
    int t = threadIdx.x;
    sw[t]       = w[t];
    sw[t + 32]  = w[t + 32];
    if (t < KOUT) sb[t] = bias[t];
    __syncwarp();

    int bimg = blockIdx.x >> 9;               // image index (0..7), 512 blocks/image
    int blk  = blockIdx.x & (BLKPI - 1);      // block within image
    int p0   = blk * VPB + t;                 // first vec position; others at +TPB..+3TPB

    const float4* ip = in4 + ((long)bimg * CCH) * HW4 + p0;
    float4*       op = out4 + ((long)bimg * KOUT) * HW4 + p0;

    #pragma unroll
    for (int k = 0; k < KOUT; k++) {
        const int c0 = kGroupStart[k];
        const int c1 = kGroupStart[k + 1];
        float bk = sb[k];
        float4 a0 = make_float4(bk, bk, bk, bk);
        float4 a1 = a0, a2 = a0, a3 = a0;
        #pragma unroll
        for (int c = c0; c < c1; c++) {
            const float4* p = ip + (long)c * HW4;
            float4 v0 = __ldcs(p);
            float4 v1 = __ldcs(p + TPB);
            float4 v2 = __ldcs(p + 2 * TPB);
            float4 v3 = __ldcs(p + 3 * TPB);
            float  wc = sw[c];
            a0.x = fmaf(wc, v0.x, a0.x); a0.y = fmaf(wc, v0.y, a0.y);
            a0.z = fmaf(wc, v0.z, a0.z); a0.w = fmaf(wc, v0.w, a0.w);
            a1.x = fmaf(wc, v1.x, a1.x); a1.y = fmaf(wc, v1.y, a1.y);
            a1.z = fmaf(wc, v1.z, a1.z); a1.w = fmaf(wc, v1.w, a1.w);
            a2.x = fmaf(wc, v2.x, a2.x); a2.y = fmaf(wc, v2.y, a2.y);
            a2.z = fmaf(wc, v2.z, a2.z); a2.w = fmaf(wc, v2.w, a2.w);
            a3.x = fmaf(wc, v3.x, a3.x); a3.y = fmaf(wc, v3.y, a3.y);
            a3.z = fmaf(wc, v3.z, a3.z); a3.w = fmaf(wc, v3.w, a3.w);
        }
        float4* q = op + (long)k * HW4;
        __stcs(q, a0);
        __stcs(q + TPB, a1);
        __stcs(q + 2 * TPB, a2);
        __stcs(q + 3 * TPB, a3);
    }
}

extern "C" void kernel_launch(void* const* d_in, const int* in_sizes, int n_in,
                              void* d_out, int out_size)
{
    const float* pred_lr = (const float*)d_in[0];   // [8,64,512,512]
    const float* weights = (const float*)d_in[1];   // [64]
    const float* biases  = (const float*)d_in[2];   // [12]
    float* out = (float*)d_out;                     // [8,12,512,512]

    int blocks = 8 * BLKPI;                         // 4096

    hier_invert_kernel<<<blocks, TPB>>>(
        (const float4*)pred_lr, weights, biases, (float4*)out);
}